// round 13
// baseline (speedup 1.0000x reference)
#include <cuda_runtime.h>
#include <cuda_bf16.h>
#include <math.h>
#include <stdint.h>

// ---------------- problem constants ----------------
#define BATCH    2
#define SEQLEN   4096
#define DMODEL   1024
#define DINNER   2048
#define DSTATE   64
#define NHEADS   16
#define HEADDIM  128
#define DCONV    4
#define CONVDIM  (DINNER + 2 * DSTATE)          // 2176
#define DINPROJ  (2*DINNER + 2*DSTATE + NHEADS) // 4240
#define NPAD1    4352                           // 34 * 128
#define ROWS     (BATCH * SEQLEN)               // 8192
#define RMS_EPS  1e-5f
#define LC       256                            // scan chunk length
#define NC       (SEQLEN / LC)                  // 16 chunks

// ---------------- scratch (no allocs allowed) ----------------
__device__ float g_zxbcdt[(size_t)ROWS * DINPROJ];
__device__ float g_xbc[(size_t)ROWS * CONVDIM];
__device__ float g_dt[(size_t)ROWS * NHEADS];
__device__ float g_y[(size_t)ROWS * DINNER];

__device__ float g_S[(size_t)BATCH * NHEADS * NC * HEADDIM * DSTATE];
__device__ float g_hinit[(size_t)BATCH * NHEADS * NC * HEADDIM * DSTATE];
__device__ float g_cum[(size_t)BATCH * NHEADS * SEQLEN];

__device__ __nv_bfloat16 g_uhi[(size_t)ROWS * DMODEL];
__device__ __nv_bfloat16 g_ulo[(size_t)ROWS * DMODEL];
__device__ __nv_bfloat16 g_w1hi[(size_t)NPAD1 * DMODEL];
__device__ __nv_bfloat16 g_w1lo[(size_t)NPAD1 * DMODEL];
__device__ __nv_bfloat16 g_yhi[(size_t)ROWS * DINNER];
__device__ __nv_bfloat16 g_ylo[(size_t)ROWS * DINNER];
__device__ __nv_bfloat16 g_w2hi[(size_t)DMODEL * DINNER];
__device__ __nv_bfloat16 g_w2lo[(size_t)DMODEL * DINNER];

// ================= helpers =================
__device__ __forceinline__ uint32_t smem_u32(const void* p) {
    uint32_t a;
    asm("{ .reg .u64 t; cvta.to.shared.u64 t, %1; cvt.u32.u64 %0, t; }" : "=r"(a) : "l"(p));
    return a;
}
__device__ __forceinline__ void cp16(uint32_t dst, const void* src) {
    asm volatile("cp.async.ca.shared.global [%0], [%1], 16;" :: "r"(dst), "l"(src));
}
__device__ __forceinline__ void cp_commit() {
    asm volatile("cp.async.commit_group;" ::: "memory");
}
template <int N>
__device__ __forceinline__ void cp_wait() {
    asm volatile("cp.async.wait_group %0;" :: "n"(N) : "memory");
}
__device__ __forceinline__ void ldmx4(uint32_t addr, uint32_t& r0, uint32_t& r1,
                                      uint32_t& r2, uint32_t& r3) {
    asm volatile("ldmatrix.sync.aligned.m8n8.x4.shared.b16 {%0,%1,%2,%3}, [%4];"
                 : "=r"(r0), "=r"(r1), "=r"(r2), "=r"(r3) : "r"(addr));
}
__device__ __forceinline__ void mma_bf16(float& d0, float& d1, float& d2, float& d3,
                                         uint32_t a0, uint32_t a1, uint32_t a2, uint32_t a3,
                                         uint32_t b0, uint32_t b1) {
    asm volatile(
        "mma.sync.aligned.m16n8k16.row.col.f32.bf16.bf16.f32 "
        "{%0,%1,%2,%3}, {%4,%5,%6,%7}, {%8,%9}, {%0,%1,%2,%3};"
        : "+f"(d0), "+f"(d1), "+f"(d2), "+f"(d3)
        : "r"(a0), "r"(a1), "r"(a2), "r"(a3), "r"(b0), "r"(b1));
}

// ================= split fp32 -> bf16 hi/lo =================
__global__ void split_hilo(const float* __restrict__ src, __nv_bfloat16* __restrict__ hi,
                           __nv_bfloat16* __restrict__ lo, long long n_src, long long n_pad)
{
    long long i = ((long long)blockIdx.x * blockDim.x + threadIdx.x) * 2;
    if (i >= n_pad) return;
    float x0 = (i     < n_src) ? src[i]     : 0.f;
    float x1 = (i + 1 < n_src) ? src[i + 1] : 0.f;
    __nv_bfloat16 h0 = __float2bfloat16(x0);
    __nv_bfloat16 h1 = __float2bfloat16(x1);
    float r0 = x0 - __bfloat162float(h0);
    float r1 = x1 - __bfloat162float(h1);
    *(__nv_bfloat162*)(hi + i) = __halves2bfloat162(h0, h1);
    *(__nv_bfloat162*)(lo + i) = __halves2bfloat162(__float2bfloat16(r0), __float2bfloat16(r1));
}

// ================= fused mma.sync bf16x3 GEMM: C = A*B^T (fp32 accum) =================
// 128x128 tile, BK=32 per chunk. 2-stage cp.async pipeline, 80KB SMEM per CTA ->
// 2 CTAs co-resident per SM (cross-CTA latency hiding over barriers/cp-waits).
// __launch_bounds__(256,2) caps regs at 128; B fragments loaded per nt-group to
// keep liveness low. 8 warps (4M x 2N; 32x64 per warp), 80B row stride.
#define TILEB  (128 * 80)          // 10240 bytes per tile
#define STAGEB (4 * TILEB)         // Ahi, Alo, Bhi, Blo
#define NSTAGE 2
#define GEMM_SMEM (NSTAGE * STAGEB)   // 81920

__global__ __launch_bounds__(256, 2)
void gemm_fused(const __nv_bfloat16* __restrict__ Ahi, const __nv_bfloat16* __restrict__ Alo,
                const __nv_bfloat16* __restrict__ Bhi, const __nv_bfloat16* __restrict__ Blo,
                float* __restrict__ C, int K, int N, int ldc)
{
    extern __shared__ __align__(16) char dynsm[];
    const uint32_t smbase = smem_u32(dynsm);

    const int tid  = threadIdx.x;
    const int wid  = tid >> 5;
    const int lane = tid & 31;
    const int m0 = blockIdx.y * 128;
    const int n0 = blockIdx.x * 128;

    const int mbase = (wid & 3) * 32;
    const int nbase = (wid >> 2) * 64;

    const int lrow  = tid >> 1;
    const int lhalf = tid & 1;

    const int kc = K >> 5;

    float acc[2][8][4];
#pragma unroll
    for (int mt = 0; mt < 2; mt++)
#pragma unroll
        for (int j = 0; j < 8; j++)
#pragma unroll
            for (int q = 0; q < 4; q++) acc[mt][j][q] = 0.f;

    const __nv_bfloat16* srcs[4];
    srcs[0] = Ahi + (size_t)(m0 + lrow) * K + lhalf * 16;
    srcs[1] = Alo + (size_t)(m0 + lrow) * K + lhalf * 16;
    srcs[2] = Bhi + (size_t)(n0 + lrow) * K + lhalf * 16;
    srcs[3] = Blo + (size_t)(n0 + lrow) * K + lhalf * 16;
    const uint32_t dsto = lrow * 80 + lhalf * 32;

    auto prefetch = [&](int c, int st) {
        const int k0 = c << 5;
        uint32_t sb = smbase + st * STAGEB + dsto;
#pragma unroll
        for (int t = 0; t < 4; t++) {
            const __nv_bfloat16* g = srcs[t] + k0;
            cp16(sb,      g);
            cp16(sb + 16, g + 8);
            sb += TILEB;
        }
    };

    prefetch(0, 0); cp_commit();

    const uint32_t rsel  = (lane & 15);
    const uint32_t cselo = (lane >> 4) * 16;

    for (int c = 0; c < kc; ++c) {
        const int st = c & 1;
        if (c + 1 < kc) {
            prefetch(c + 1, st ^ 1);   // stage st^1 was released at end of iter c-1
            cp_commit();
            cp_wait<1>();              // ensure chunk c's group is complete
        } else {
            cp_wait<0>();
        }
        __syncthreads();

        const uint32_t aHiB = smbase + st * STAGEB;
        const uint32_t aLoB = aHiB + TILEB;
        const uint32_t bHiB = aLoB + TILEB;
        const uint32_t bLoB = bHiB + TILEB;

#pragma unroll
        for (int s = 0; s < 2; ++s) {        // two k16 steps in BK=32
            const uint32_t so = s * 32 + cselo;
            uint32_t ah[2][4], al[2][4];
#pragma unroll
            for (int mt = 0; mt < 2; mt++) {
                const uint32_t ro = (mbase + mt * 16 + rsel) * 80 + so;
                ldmx4(aHiB + ro, ah[mt][0], ah[mt][1], ah[mt][2], ah[mt][3]);
                ldmx4(aLoB + ro, al[mt][0], al[mt][1], al[mt][2], al[mt][3]);
            }
            // per nt-group B fragments (keeps b-liveness at 8 regs)
#pragma unroll
            for (int nt = 0; nt < 4; nt++) {
                const uint32_t ro = (nbase + nt * 16 + rsel) * 80 + so;
                uint32_t h0, h1, h2, h3, l0, l1, l2, l3;
                ldmx4(bHiB + ro, h0, h1, h2, h3);
                ldmx4(bLoB + ro, l0, l1, l2, l3);
                const int j0 = nt * 2, j1 = nt * 2 + 1;
                // pass hi*hi
#pragma unroll
                for (int mt = 0; mt < 2; mt++) {
                    mma_bf16(acc[mt][j0][0], acc[mt][j0][1], acc[mt][j0][2], acc[mt][j0][3],
                             ah[mt][0], ah[mt][1], ah[mt][2], ah[mt][3], h0, h2);
                    mma_bf16(acc[mt][j1][0], acc[mt][j1][1], acc[mt][j1][2], acc[mt][j1][3],
                             ah[mt][0], ah[mt][1], ah[mt][2], ah[mt][3], h1, h3);
                }
                // pass lo*hi
#pragma unroll
                for (int mt = 0; mt < 2; mt++) {
                    mma_bf16(acc[mt][j0][0], acc[mt][j0][1], acc[mt][j0][2], acc[mt][j0][3],
                             al[mt][0], al[mt][1], al[mt][2], al[mt][3], h0, h2);
                    mma_bf16(acc[mt][j1][0], acc[mt][j1][1], acc[mt][j1][2], acc[mt][j1][3],
                             al[mt][0], al[mt][1], al[mt][2], al[mt][3], h1, h3);
                }
                // pass hi*lo
#pragma unroll
                for (int mt = 0; mt < 2; mt++) {
                    mma_bf16(acc[mt][j0][0], acc[mt][j0][1], acc[mt][j0][2], acc[mt][j0][3],
                             ah[mt][0], ah[mt][1], ah[mt][2], ah[mt][3], l0, l2);
                    mma_bf16(acc[mt][j1][0], acc[mt][j1][1], acc[mt][j1][2], acc[mt][j1][3],
                             ah[mt][0], ah[mt][1], ah[mt][2], ah[mt][3], l1, l3);
                }
            }
        }
        __syncthreads();
    }

    // epilogue
#pragma unroll
    for (int mt = 0; mt < 2; mt++) {
        const int rlo = m0 + mbase + mt * 16 + (lane >> 2);
#pragma unroll
        for (int j = 0; j < 8; j++) {
            const int col = n0 + nbase + j * 8 + 2 * (lane & 3);
            if (col < N) {
                *(float2*)(C + (size_t)rlo * ldc + col) =
                    make_float2(acc[mt][j][0], acc[mt][j][1]);
                *(float2*)(C + (size_t)(rlo + 8) * ldc + col) =
                    make_float2(acc[mt][j][2], acc[mt][j][3]);
            }
        }
    }
}

// ================= causal depthwise conv(4) + SiLU =================
__global__ void conv_silu_kernel(const float* __restrict__ zx,
                                 const float* __restrict__ cw,
                                 const float* __restrict__ cb,
                                 float* __restrict__ out)
{
    const long long idx = (long long)blockIdx.x * blockDim.x + threadIdx.x;
    const long long total = (long long)ROWS * CONVDIM;
    if (idx >= total) return;
    const int c  = (int)(idx % CONVDIM);
    const int bl = (int)(idx / CONVDIM);
    const int l  = bl % SEQLEN;
    const int b  = bl / SEQLEN;

    const float* src = zx + ((size_t)b * SEQLEN) * DINPROJ + DINNER + c;
    float acc = cb[c];
#pragma unroll
    for (int k = 0; k < DCONV; k++) {
        const int li = l - (DCONV - 1) + k;
        if (li >= 0) acc = fmaf(cw[c * DCONV + k], src[(size_t)li * DINPROJ], acc);
    }
    out[idx] = acc / (1.f + expf(-acc));
}

// ================= dt = softplus(raw + bias) =================
__global__ void dt_kernel(const float* __restrict__ zx,
                          const float* __restrict__ dt_bias,
                          float* __restrict__ dt)
{
    const int idx = blockIdx.x * blockDim.x + threadIdx.x;
    if (idx >= ROWS * NHEADS) return;
    const int h  = idx % NHEADS;
    const int bl = idx / NHEADS;
    float v = zx[(size_t)bl * DINPROJ + (DINPROJ - NHEADS) + h] + dt_bias[h];
    dt[idx] = (v > 20.f) ? v : log1pf(expf(v));
}

// ================= Phase 1: chunk-local scan =================
__global__ __launch_bounds__(256, 1)
void scan_chunk(const float* __restrict__ xbc, const float* __restrict__ dtb_,
                const float* __restrict__ A_log, const float* __restrict__ Dv,
                float* __restrict__ y, float* __restrict__ Sout,
                float* __restrict__ cumout)
{
    const int c   = blockIdx.x & (NC - 1);
    const int bh  = blockIdx.x >> 4;
    const int h   = bh & 15;
    const int b   = bh >> 4;
    const int tid = threadIdx.x;
    const int p   = tid & 127;
    const int half = tid >> 7;
    const int nb  = half * 32;
    const int t0  = c * LC;

    const float Ah = -expf(A_log[h]);
    const float Dh = Dv[h];

    __shared__ float Bsh[2][64];
    __shared__ float Csh[2][64];
    __shared__ float dts[2];
    __shared__ float yred[128];

    const float* xb  = xbc + (size_t)b * SEQLEN * CONVDIM;
    const float* dtp = dtb_ + (size_t)b * SEQLEN * NHEADS + h;

    float s[32];
#pragma unroll
    for (int i = 0; i < 32; i++) s[i] = 0.f;

    {
        const size_t base = (size_t)t0 * CONVDIM;
        if (tid < 64)        Bsh[0][tid]      = xb[base + DINNER + tid];
        else if (tid < 128)  Csh[0][tid - 64] = xb[base + DINNER + DSTATE + (tid - 64)];
        else if (tid == 128) dts[0]           = dtp[(size_t)t0 * NHEADS];
    }
    __syncthreads();

    float cum = 1.f;
    for (int tt = 0; tt < LC; tt++) {
        const int t   = t0 + tt;
        const int buf = tt & 1;
        const float x = xb[(size_t)t * CONVDIM + h * HEADDIM + p];
        const float decay = expf(dts[buf] * Ah);
        cum *= decay;

        if (tt + 1 < LC) {
            const int nbuf = buf ^ 1;
            const size_t base = (size_t)(t + 1) * CONVDIM;
            if (tid < 64)        Bsh[nbuf][tid]      = xb[base + DINNER + tid];
            else if (tid < 128)  Csh[nbuf][tid - 64] = xb[base + DINNER + DSTATE + (tid - 64)];
            else if (tid == 128) dts[nbuf]           = dtp[(size_t)(t + 1) * NHEADS];
        }

        float yp = 0.f;
        const float4* B4 = (const float4*)&Bsh[buf][nb];
        const float4* C4 = (const float4*)&Csh[buf][nb];
#pragma unroll
        for (int i = 0; i < 8; i++) {
            const float4 bv = B4[i];
            const float4 cv = C4[i];
            s[4*i+0] = fmaf(bv.x, x, decay * s[4*i+0]); yp = fmaf(s[4*i+0], cv.x, yp);
            s[4*i+1] = fmaf(bv.y, x, decay * s[4*i+1]); yp = fmaf(s[4*i+1], cv.y, yp);
            s[4*i+2] = fmaf(bv.z, x, decay * s[4*i+2]); yp = fmaf(s[4*i+2], cv.z, yp);
            s[4*i+3] = fmaf(bv.w, x, decay * s[4*i+3]); yp = fmaf(s[4*i+3], cv.w, yp);
        }

        if (tid == 255) cumout[(size_t)bh * SEQLEN + t] = cum;

        if (half) yred[p] = yp;
        __syncthreads();
        if (!half) {
            const float out = yp + yred[p] + Dh * x;
            y[((size_t)b * SEQLEN + t) * DINNER + h * HEADDIM + p] = out;
        }
        __syncthreads();
    }

    {
        float* Sp = Sout + (((size_t)(bh * NC + c)) << 13) + p * 64 + nb;
#pragma unroll
        for (int i = 0; i < 32; i += 4)
            *(float4*)(Sp + i) = make_float4(s[i], s[i+1], s[i+2], s[i+3]);
    }
}

// ================= Phase 2: inter-chunk state prefix =================
__global__ __launch_bounds__(256)
void chunk_prefix(const float* __restrict__ S, const float* __restrict__ cumb,
                  float* __restrict__ hinit)
{
    const int bh  = blockIdx.x;
    const int tid = threadIdx.x;

    float hreg[32];
#pragma unroll
    for (int j = 0; j < 32; j++) hreg[j] = 0.f;

    for (int c = 0; c < NC; c++) {
        const float Ac = cumb[(size_t)bh * SEQLEN + c * LC + LC - 1];
        const size_t base = ((size_t)(bh * NC + c)) << 13;
#pragma unroll
        for (int j = 0; j < 32; j++) {
            const size_t idx = base + tid + 256 * j;
            hinit[idx] = hreg[j];
            hreg[j] = fmaf(Ac, hreg[j], S[idx]);
        }
    }
}

// ================= Phase 3: y += cum_t * (C_t . h_init) =================
__global__ __launch_bounds__(256)
void y_correct(const float* __restrict__ xbc, const float* __restrict__ hinit,
               const float* __restrict__ cumb, float* __restrict__ y)
{
    const int c = blockIdx.x & (NC - 1);
    if (c == 0) return;
    const int bh  = blockIdx.x >> 4;
    const int h   = bh & 15;
    const int b   = bh >> 4;
    const int tid = threadIdx.x;
    const int p   = tid >> 1;
    const int nh  = (tid & 1) * 32;
    const int t0  = c * LC;

    __shared__ float Cs[2][64];

    float hreg[32];
    {
        const float* hp = hinit + (((size_t)(bh * NC + c)) << 13) + p * 64 + nh;
#pragma unroll
        for (int i = 0; i < 32; i += 4) {
            float4 v = *(const float4*)(hp + i);
            hreg[i] = v.x; hreg[i+1] = v.y; hreg[i+2] = v.z; hreg[i+3] = v.w;
        }
    }

    const float* xb = xbc + (size_t)b * SEQLEN * CONVDIM;
    if (tid < 64) Cs[0][tid] = xb[(size_t)t0 * CONVDIM + DINNER + DSTATE + tid];
    __syncthreads();

    const float* cumrow = cumb + (size_t)bh * SEQLEN;

    for (int tt = 0; tt < LC; tt++) {
        const int t   = t0 + tt;
        const int buf = tt & 1;
        if (tt + 1 < LC && tid < 64)
            Cs[buf ^ 1][tid] = xb[(size_t)(t + 1) * CONVDIM + DINNER + DSTATE + tid];

        float dot = 0.f;
        const float4* C4 = (const float4*)&Cs[buf][nh];
#pragma unroll
        for (int k = 0; k < 8; k++) {
            const float4 cv = C4[k];
            dot = fmaf(hreg[4*k+0], cv.x, dot);
            dot = fmaf(hreg[4*k+1], cv.y, dot);
            dot = fmaf(hreg[4*k+2], cv.z, dot);
            dot = fmaf(hreg[4*k+3], cv.w, dot);
        }
        dot += __shfl_xor_sync(0xffffffffu, dot, 1);

        if ((tid & 1) == 0) {
            float* yp = y + ((size_t)b * SEQLEN + t) * DINNER + h * HEADDIM + p;
            *yp += cumrow[t] * dot;
        }
        __syncthreads();
    }
}

// ================= RMSNorm + SiLU(z) gate -> bf16 hi/lo =================
__global__ __launch_bounds__(256)
void rmsgate_kernel(const float* __restrict__ y, const float* __restrict__ zx,
                    const float* __restrict__ w,
                    __nv_bfloat16* __restrict__ yhi, __nv_bfloat16* __restrict__ ylo)
{
    const int row = blockIdx.x;
    const float* yr = y + (size_t)row * DINNER;
    const float* zr = zx + (size_t)row * DINPROJ;
    const int tid = threadIdx.x;

    float vals[8];
    float ss = 0.f;
#pragma unroll
    for (int i = 0; i < 8; i++) {
        const float v = yr[tid + 256 * i];
        vals[i] = v;
        ss = fmaf(v, v, ss);
    }

    __shared__ float red[256];
    red[tid] = ss;
    __syncthreads();
#pragma unroll
    for (int s = 128; s > 0; s >>= 1) {
        if (tid < s) red[tid] += red[tid + s];
        __syncthreads();
    }
    const float scale = rsqrtf(red[0] / (float)DINNER + RMS_EPS);

#pragma unroll
    for (int i = 0; i < 8; i++) {
        const int c = tid + 256 * i;
        const float zv = zr[c];
        const float gate = 1.f / (1.f + expf(-zv));
        const float out = vals[i] * scale * w[c] * gate;
        const __nv_bfloat16 h = __float2bfloat16(out);
        yhi[(size_t)row * DINNER + c] = h;
        ylo[(size_t)row * DINNER + c] = __float2bfloat16(out - __bfloat162float(h));
    }
}

// ================= launch =================
extern "C" void kernel_launch(void* const* d_in, const int* in_sizes, int n_in,
                              void* d_out, int out_size)
{
    const float* u         = (const float*)d_in[0];
    const float* in_proj_w = (const float*)d_in[1];
    const float* conv_w    = (const float*)d_in[2];
    const float* conv_b    = (const float*)d_in[3];
    const float* dt_bias   = (const float*)d_in[4];
    const float* A_log     = (const float*)d_in[5];
    const float* Dv        = (const float*)d_in[6];
    const float* rms_w     = (const float*)d_in[7];
    const float* out_w     = (const float*)d_in[8];
    float* out = (float*)d_out;

    float *zx, *xbc, *dt, *y, *Sb, *hinit, *cum;
    cudaGetSymbolAddress((void**)&zx,    g_zxbcdt);
    cudaGetSymbolAddress((void**)&xbc,   g_xbc);
    cudaGetSymbolAddress((void**)&dt,    g_dt);
    cudaGetSymbolAddress((void**)&y,     g_y);
    cudaGetSymbolAddress((void**)&Sb,    g_S);
    cudaGetSymbolAddress((void**)&hinit, g_hinit);
    cudaGetSymbolAddress((void**)&cum,   g_cum);

    __nv_bfloat16 *uhi, *ulo, *w1hi, *w1lo, *yhi, *ylo, *w2hi, *w2lo;
    cudaGetSymbolAddress((void**)&uhi,  g_uhi);
    cudaGetSymbolAddress((void**)&ulo,  g_ulo);
    cudaGetSymbolAddress((void**)&w1hi, g_w1hi);
    cudaGetSymbolAddress((void**)&w1lo, g_w1lo);
    cudaGetSymbolAddress((void**)&yhi,  g_yhi);
    cudaGetSymbolAddress((void**)&ylo,  g_ylo);
    cudaGetSymbolAddress((void**)&w2hi, g_w2hi);
    cudaGetSymbolAddress((void**)&w2lo, g_w2lo);

    cudaFuncSetAttribute(gemm_fused, cudaFuncAttributeMaxDynamicSharedMemorySize, GEMM_SMEM);

    // 1) splits for GEMM1
    {
        long long n = (long long)ROWS * DMODEL;
        split_hilo<<<(unsigned)((n/2 + 255) / 256), 256>>>(u, uhi, ulo, n, n);
        long long ns = (long long)DINPROJ * DMODEL;
        long long np = (long long)NPAD1 * DMODEL;
        split_hilo<<<(unsigned)((np/2 + 255) / 256), 256>>>(in_proj_w, w1hi, w1lo, ns, np);
    }
    // 2) in_proj GEMM: zx[8192,4240] = u * W1^T
    {
        dim3 grid(NPAD1 / 128, ROWS / 128);
        gemm_fused<<<grid, 256, GEMM_SMEM>>>(uhi, ulo, w1hi, w1lo, zx, DMODEL, DINPROJ, DINPROJ);
    }
    // 3) conv + silu
    {
        const long long total = (long long)ROWS * CONVDIM;
        conv_silu_kernel<<<(unsigned)((total + 255) / 256), 256>>>(zx, conv_w, conv_b, xbc);
    }
    // 4) dt softplus
    dt_kernel<<<(ROWS * NHEADS + 255) / 256, 256>>>(zx, dt_bias, dt);
    // 5) chunk-parallel scan
    scan_chunk<<<BATCH * NHEADS * NC, 256>>>(xbc, dt, A_log, Dv, y, Sb, cum);
    chunk_prefix<<<BATCH * NHEADS, 256>>>(Sb, cum, hinit);
    y_correct<<<BATCH * NHEADS * NC, 256>>>(xbc, hinit, cum, y);
    // 6) rmsnorm + gate -> bf16 hi/lo directly
    rmsgate_kernel<<<ROWS, 256>>>(y, zx, rms_w, yhi, ylo);
    // 7) split for GEMM2 weights
    {
        long long nw = (long long)DMODEL * DINNER;
        split_hilo<<<(unsigned)((nw/2 + 255) / 256), 256>>>(out_w, w2hi, w2lo, nw, nw);
    }
    // 8) out_proj GEMM: out[8192,1024] = y_gated * W2^T
    {
        dim3 grid(DMODEL / 128, ROWS / 128);
        gemm_fused<<<grid, 256, GEMM_SMEM>>>(yhi, ylo, w2hi, w2lo, out, DINNER, DMODEL, DMODEL);
    }
}

// round 14
// speedup vs baseline: 1.7629x; 1.7629x over previous
#include <cuda_runtime.h>
#include <cuda_fp16.h>
#include <math.h>
#include <stdint.h>

// ---------------- problem constants ----------------
#define BATCH    2
#define SEQLEN   4096
#define DMODEL   1024
#define DINNER   2048
#define DSTATE   64
#define NHEADS   16
#define HEADDIM  128
#define DCONV    4
#define CONVDIM  (DINNER + 2 * DSTATE)          // 2176
#define DINPROJ  (2*DINNER + 2*DSTATE + NHEADS) // 4240
#define NPAD1    4352                           // 34 * 128
#define ROWS     (BATCH * SEQLEN)               // 8192
#define RMS_EPS  1e-5f
#define LC       256                            // scan chunk length
#define NC       (SEQLEN / LC)                  // 16 chunks

// ---------------- scratch (no allocs allowed) ----------------
__device__ float g_zxbcdt[(size_t)ROWS * DINPROJ];
__device__ float g_xbc[(size_t)ROWS * CONVDIM];
__device__ float g_dt[(size_t)ROWS * NHEADS];
__device__ float g_y[(size_t)ROWS * DINNER];

__device__ float g_S[(size_t)BATCH * NHEADS * NC * HEADDIM * DSTATE];
__device__ float g_hinit[(size_t)BATCH * NHEADS * NC * HEADDIM * DSTATE];
__device__ float g_cum[(size_t)BATCH * NHEADS * SEQLEN];

__device__ __half g_uhi[(size_t)ROWS * DMODEL];
__device__ __half g_ulo[(size_t)ROWS * DMODEL];
__device__ __half g_w1hi[(size_t)NPAD1 * DMODEL];
__device__ __half g_yhi[(size_t)ROWS * DINNER];
__device__ __half g_ylo[(size_t)ROWS * DINNER];
__device__ __half g_w2hi[(size_t)DMODEL * DINNER];

// ================= helpers =================
__device__ __forceinline__ uint32_t smem_u32(const void* p) {
    uint32_t a;
    asm("{ .reg .u64 t; cvta.to.shared.u64 t, %1; cvt.u32.u64 %0, t; }" : "=r"(a) : "l"(p));
    return a;
}
__device__ __forceinline__ void cp16(uint32_t dst, const void* src) {
    asm volatile("cp.async.ca.shared.global [%0], [%1], 16;" :: "r"(dst), "l"(src));
}
__device__ __forceinline__ void cp_commit() {
    asm volatile("cp.async.commit_group;" ::: "memory");
}
template <int N>
__device__ __forceinline__ void cp_wait() {
    asm volatile("cp.async.wait_group %0;" :: "n"(N) : "memory");
}
__device__ __forceinline__ void ldmx4(uint32_t addr, uint32_t& r0, uint32_t& r1,
                                      uint32_t& r2, uint32_t& r3) {
    asm volatile("ldmatrix.sync.aligned.m8n8.x4.shared.b16 {%0,%1,%2,%3}, [%4];"
                 : "=r"(r0), "=r"(r1), "=r"(r2), "=r"(r3) : "r"(addr));
}
__device__ __forceinline__ void mma_f16(float& d0, float& d1, float& d2, float& d3,
                                        uint32_t a0, uint32_t a1, uint32_t a2, uint32_t a3,
                                        uint32_t b0, uint32_t b1) {
    asm volatile(
        "mma.sync.aligned.m16n8k16.row.col.f32.f16.f16.f32 "
        "{%0,%1,%2,%3}, {%4,%5,%6,%7}, {%8,%9}, {%0,%1,%2,%3};"
        : "+f"(d0), "+f"(d1), "+f"(d2), "+f"(d3)
        : "r"(a0), "r"(a1), "r"(a2), "r"(a3), "r"(b0), "r"(b1));
}

// ================= split fp32 -> fp16 hi/lo =================
__global__ void split_hilo(const float* __restrict__ src, __half* __restrict__ hi,
                           __half* __restrict__ lo, long long n_src)
{
    long long i = ((long long)blockIdx.x * blockDim.x + threadIdx.x) * 2;
    if (i >= n_src) return;
    float x0 = src[i];
    float x1 = src[i + 1];
    __half h0 = __float2half_rn(x0);
    __half h1 = __float2half_rn(x1);
    float r0 = x0 - __half2float(h0);
    float r1 = x1 - __half2float(h1);
    *(__half2*)(hi + i) = __halves2half2(h0, h1);
    *(__half2*)(lo + i) = __halves2half2(__float2half_rn(r0), __float2half_rn(r1));
}

// fp32 -> fp16 (hi only), with zero padding to n_pad
__global__ void to_half(const float* __restrict__ src, __half* __restrict__ dst,
                        long long n_src, long long n_pad)
{
    long long i = ((long long)blockIdx.x * blockDim.x + threadIdx.x) * 2;
    if (i >= n_pad) return;
    float x0 = (i     < n_src) ? src[i]     : 0.f;
    float x1 = (i + 1 < n_src) ? src[i + 1] : 0.f;
    *(__half2*)(dst + i) = __halves2half2(__float2half_rn(x0), __float2half_rn(x1));
}

// ================= fused mma.sync fp16x2 GEMM: C = A*B^T (fp32 accum) =================
// A = ahi + alo (22-bit effective), B = bhi (11-bit). C = ahi*bhi + alo*bhi.
// 128x128 tile, BK=32 per chunk, 3 tiles/chunk (Ahi, Alo, Bhi). 3-stage cp.async
// pipeline. 8 warps (4M x 2N; 32x64 per warp), 80B row stride (conflict-free ldmatrix).
#define TILEB  (128 * 80)          // 10240 bytes per tile
#define STAGEB (3 * TILEB)         // Ahi, Alo, Bhi
#define NSTAGE 3
#define GEMM_SMEM (NSTAGE * STAGEB)   // 92160

__global__ __launch_bounds__(256, 1)
void gemm_fused(const __half* __restrict__ Ahi, const __half* __restrict__ Alo,
                const __half* __restrict__ Bhi,
                float* __restrict__ C, int K, int N, int ldc)
{
    extern __shared__ __align__(16) char dynsm[];
    const uint32_t smbase = smem_u32(dynsm);

    const int tid  = threadIdx.x;
    const int wid  = tid >> 5;
    const int lane = tid & 31;
    const int m0 = blockIdx.y * 128;
    const int n0 = blockIdx.x * 128;

    const int mbase = (wid & 3) * 32;
    const int nbase = (wid >> 2) * 64;

    const int lrow  = tid >> 1;
    const int lhalf = tid & 1;

    const int kc = K >> 5;

    float acc[2][8][4];
#pragma unroll
    for (int mt = 0; mt < 2; mt++)
#pragma unroll
        for (int j = 0; j < 8; j++)
#pragma unroll
            for (int q = 0; q < 4; q++) acc[mt][j][q] = 0.f;

    const __half* srcs[3];
    srcs[0] = Ahi + (size_t)(m0 + lrow) * K + lhalf * 16;
    srcs[1] = Alo + (size_t)(m0 + lrow) * K + lhalf * 16;
    srcs[2] = Bhi + (size_t)(n0 + lrow) * K + lhalf * 16;
    const uint32_t dsto = lrow * 80 + lhalf * 32;

    auto prefetch = [&](int c, int st) {
        const int k0 = c << 5;
        uint32_t sb = smbase + st * STAGEB + dsto;
#pragma unroll
        for (int t = 0; t < 3; t++) {
            const __half* g = srcs[t] + k0;
            cp16(sb,      g);
            cp16(sb + 16, g + 8);
            sb += TILEB;
        }
    };

    prefetch(0, 0); cp_commit();
    if (kc > 1) { prefetch(1, 1); cp_commit(); }

    const uint32_t rsel  = (lane & 15);
    const uint32_t cselo = (lane >> 4) * 16;

    for (int c = 0; c < kc; ++c) {
        const int st = c % NSTAGE;
        if (c + 2 < kc) {
            prefetch(c + 2, (c + 2) % NSTAGE);
            cp_commit();
            cp_wait<2>();
        } else {
            cp_wait<0>();
        }
        __syncthreads();

        const uint32_t aHiB = smbase + st * STAGEB;
        const uint32_t aLoB = aHiB + TILEB;
        const uint32_t bHiB = aLoB + TILEB;

#pragma unroll
        for (int s = 0; s < 2; ++s) {        // two k16 steps in BK=32
            const uint32_t so = s * 32 + cselo;
            uint32_t ah[2][4], al[2][4];
#pragma unroll
            for (int mt = 0; mt < 2; mt++) {
                const uint32_t ro = (mbase + mt * 16 + rsel) * 80 + so;
                ldmx4(aHiB + ro, ah[mt][0], ah[mt][1], ah[mt][2], ah[mt][3]);
                ldmx4(aLoB + ro, al[mt][0], al[mt][1], al[mt][2], al[mt][3]);
            }
            uint32_t bh[8][2];
#pragma unroll
            for (int nt = 0; nt < 4; nt++) {
                const uint32_t ro = (nbase + nt * 16 + rsel) * 80 + so;
                uint32_t r0, r1, r2, r3;
                ldmx4(bHiB + ro, r0, r1, r2, r3);
                bh[nt * 2][0] = r0; bh[nt * 2][1] = r2;
                bh[nt * 2 + 1][0] = r1; bh[nt * 2 + 1][1] = r3;
            }
            // pass 1: hi*hi
#pragma unroll
            for (int mt = 0; mt < 2; mt++)
#pragma unroll
                for (int j = 0; j < 8; j++)
                    mma_f16(acc[mt][j][0], acc[mt][j][1], acc[mt][j][2], acc[mt][j][3],
                            ah[mt][0], ah[mt][1], ah[mt][2], ah[mt][3],
                            bh[j][0], bh[j][1]);
            // pass 2: lo*hi
#pragma unroll
            for (int mt = 0; mt < 2; mt++)
#pragma unroll
                for (int j = 0; j < 8; j++)
                    mma_f16(acc[mt][j][0], acc[mt][j][1], acc[mt][j][2], acc[mt][j][3],
                            al[mt][0], al[mt][1], al[mt][2], al[mt][3],
                            bh[j][0], bh[j][1]);
        }
        __syncthreads();
    }

    // epilogue
#pragma unroll
    for (int mt = 0; mt < 2; mt++) {
        const int rlo = m0 + mbase + mt * 16 + (lane >> 2);
#pragma unroll
        for (int j = 0; j < 8; j++) {
            const int col = n0 + nbase + j * 8 + 2 * (lane & 3);
            if (col < N) {
                *(float2*)(C + (size_t)rlo * ldc + col) =
                    make_float2(acc[mt][j][0], acc[mt][j][1]);
                *(float2*)(C + (size_t)(rlo + 8) * ldc + col) =
                    make_float2(acc[mt][j][2], acc[mt][j][3]);
            }
        }
    }
}

// ================= causal depthwise conv(4) + SiLU =================
__global__ void conv_silu_kernel(const float* __restrict__ zx,
                                 const float* __restrict__ cw,
                                 const float* __restrict__ cb,
                                 float* __restrict__ out)
{
    const long long idx = (long long)blockIdx.x * blockDim.x + threadIdx.x;
    const long long total = (long long)ROWS * CONVDIM;
    if (idx >= total) return;
    const int c  = (int)(idx % CONVDIM);
    const int bl = (int)(idx / CONVDIM);
    const int l  = bl % SEQLEN;
    const int b  = bl / SEQLEN;

    const float* src = zx + ((size_t)b * SEQLEN) * DINPROJ + DINNER + c;
    float acc = cb[c];
#pragma unroll
    for (int k = 0; k < DCONV; k++) {
        const int li = l - (DCONV - 1) + k;
        if (li >= 0) acc = fmaf(cw[c * DCONV + k], src[(size_t)li * DINPROJ], acc);
    }
    out[idx] = acc / (1.f + expf(-acc));
}

// ================= dt = softplus(raw + bias) =================
__global__ void dt_kernel(const float* __restrict__ zx,
                          const float* __restrict__ dt_bias,
                          float* __restrict__ dt)
{
    const int idx = blockIdx.x * blockDim.x + threadIdx.x;
    if (idx >= ROWS * NHEADS) return;
    const int h  = idx % NHEADS;
    const int bl = idx / NHEADS;
    float v = zx[(size_t)bl * DINPROJ + (DINPROJ - NHEADS) + h] + dt_bias[h];
    dt[idx] = (v > 20.f) ? v : log1pf(expf(v));
}

// ================= Phase 1: chunk-local scan =================
__global__ __launch_bounds__(256, 1)
void scan_chunk(const float* __restrict__ xbc, const float* __restrict__ dtb_,
                const float* __restrict__ A_log, const float* __restrict__ Dv,
                float* __restrict__ y, float* __restrict__ Sout,
                float* __restrict__ cumout)
{
    const int c   = blockIdx.x & (NC - 1);
    const int bh  = blockIdx.x >> 4;
    const int h   = bh & 15;
    const int b   = bh >> 4;
    const int tid = threadIdx.x;
    const int p   = tid & 127;
    const int half = tid >> 7;
    const int nb  = half * 32;
    const int t0  = c * LC;

    const float Ah = -expf(A_log[h]);
    const float Dh = Dv[h];

    __shared__ float Bsh[2][64];
    __shared__ float Csh[2][64];
    __shared__ float dts[2];
    __shared__ float yred[128];

    const float* xb  = xbc + (size_t)b * SEQLEN * CONVDIM;
    const float* dtp = dtb_ + (size_t)b * SEQLEN * NHEADS + h;

    float s[32];
#pragma unroll
    for (int i = 0; i < 32; i++) s[i] = 0.f;

    {
        const size_t base = (size_t)t0 * CONVDIM;
        if (tid < 64)        Bsh[0][tid]      = xb[base + DINNER + tid];
        else if (tid < 128)  Csh[0][tid - 64] = xb[base + DINNER + DSTATE + (tid - 64)];
        else if (tid == 128) dts[0]           = dtp[(size_t)t0 * NHEADS];
    }
    __syncthreads();

    float cum = 1.f;
    for (int tt = 0; tt < LC; tt++) {
        const int t   = t0 + tt;
        const int buf = tt & 1;
        const float x = xb[(size_t)t * CONVDIM + h * HEADDIM + p];
        const float decay = expf(dts[buf] * Ah);
        cum *= decay;

        if (tt + 1 < LC) {
            const int nbuf = buf ^ 1;
            const size_t base = (size_t)(t + 1) * CONVDIM;
            if (tid < 64)        Bsh[nbuf][tid]      = xb[base + DINNER + tid];
            else if (tid < 128)  Csh[nbuf][tid - 64] = xb[base + DINNER + DSTATE + (tid - 64)];
            else if (tid == 128) dts[nbuf]           = dtp[(size_t)(t + 1) * NHEADS];
        }

        float yp = 0.f;
        const float4* B4 = (const float4*)&Bsh[buf][nb];
        const float4* C4 = (const float4*)&Csh[buf][nb];
#pragma unroll
        for (int i = 0; i < 8; i++) {
            const float4 bv = B4[i];
            const float4 cv = C4[i];
            s[4*i+0] = fmaf(bv.x, x, decay * s[4*i+0]); yp = fmaf(s[4*i+0], cv.x, yp);
            s[4*i+1] = fmaf(bv.y, x, decay * s[4*i+1]); yp = fmaf(s[4*i+1], cv.y, yp);
            s[4*i+2] = fmaf(bv.z, x, decay * s[4*i+2]); yp = fmaf(s[4*i+2], cv.z, yp);
            s[4*i+3] = fmaf(bv.w, x, decay * s[4*i+3]); yp = fmaf(s[4*i+3], cv.w, yp);
        }

        if (tid == 255) cumout[(size_t)bh * SEQLEN + t] = cum;

        if (half) yred[p] = yp;
        __syncthreads();
        if (!half) {
            const float out = yp + yred[p] + Dh * x;
            y[((size_t)b * SEQLEN + t) * DINNER + h * HEADDIM + p] = out;
        }
        __syncthreads();
    }

    {
        float* Sp = Sout + (((size_t)(bh * NC + c)) << 13) + p * 64 + nb;
#pragma unroll
        for (int i = 0; i < 32; i += 4)
            *(float4*)(Sp + i) = make_float4(s[i], s[i+1], s[i+2], s[i+3]);
    }
}

// ================= Phase 2: inter-chunk state prefix =================
__global__ __launch_bounds__(256)
void chunk_prefix(const float* __restrict__ S, const float* __restrict__ cumb,
                  float* __restrict__ hinit)
{
    const int bh  = blockIdx.x;
    const int tid = threadIdx.x;

    float hreg[32];
#pragma unroll
    for (int j = 0; j < 32; j++) hreg[j] = 0.f;

    for (int c = 0; c < NC; c++) {
        const float Ac = cumb[(size_t)bh * SEQLEN + c * LC + LC - 1];
        const size_t base = ((size_t)(bh * NC + c)) << 13;
#pragma unroll
        for (int j = 0; j < 32; j++) {
            const size_t idx = base + tid + 256 * j;
            hinit[idx] = hreg[j];
            hreg[j] = fmaf(Ac, hreg[j], S[idx]);
        }
    }
}

// ================= Phase 3: y += cum_t * (C_t . h_init) =================
__global__ __launch_bounds__(256)
void y_correct(const float* __restrict__ xbc, const float* __restrict__ hinit,
               const float* __restrict__ cumb, float* __restrict__ y)
{
    const int c = blockIdx.x & (NC - 1);
    if (c == 0) return;
    const int bh  = blockIdx.x >> 4;
    const int h   = bh & 15;
    const int b   = bh >> 4;
    const int tid = threadIdx.x;
    const int p   = tid >> 1;
    const int nh  = (tid & 1) * 32;
    const int t0  = c * LC;

    __shared__ float Cs[2][64];

    float hreg[32];
    {
        const float* hp = hinit + (((size_t)(bh * NC + c)) << 13) + p * 64 + nh;
#pragma unroll
        for (int i = 0; i < 32; i += 4) {
            float4 v = *(const float4*)(hp + i);
            hreg[i] = v.x; hreg[i+1] = v.y; hreg[i+2] = v.z; hreg[i+3] = v.w;
        }
    }

    const float* xb = xbc + (size_t)b * SEQLEN * CONVDIM;
    if (tid < 64) Cs[0][tid] = xb[(size_t)t0 * CONVDIM + DINNER + DSTATE + tid];
    __syncthreads();

    const float* cumrow = cumb + (size_t)bh * SEQLEN;

    for (int tt = 0; tt < LC; tt++) {
        const int t   = t0 + tt;
        const int buf = tt & 1;
        if (tt + 1 < LC && tid < 64)
            Cs[buf ^ 1][tid] = xb[(size_t)(t + 1) * CONVDIM + DINNER + DSTATE + tid];

        float dot = 0.f;
        const float4* C4 = (const float4*)&Cs[buf][nh];
#pragma unroll
        for (int k = 0; k < 8; k++) {
            const float4 cv = C4[k];
            dot = fmaf(hreg[4*k+0], cv.x, dot);
            dot = fmaf(hreg[4*k+1], cv.y, dot);
            dot = fmaf(hreg[4*k+2], cv.z, dot);
            dot = fmaf(hreg[4*k+3], cv.w, dot);
        }
        dot += __shfl_xor_sync(0xffffffffu, dot, 1);

        if ((tid & 1) == 0) {
            float* yp = y + ((size_t)b * SEQLEN + t) * DINNER + h * HEADDIM + p;
            *yp += cumrow[t] * dot;
        }
        __syncthreads();
    }
}

// ================= RMSNorm + SiLU(z) gate -> fp16 hi/lo =================
__global__ __launch_bounds__(256)
void rmsgate_kernel(const float* __restrict__ y, const float* __restrict__ zx,
                    const float* __restrict__ w,
                    __half* __restrict__ yhi, __half* __restrict__ ylo)
{
    const int row = blockIdx.x;
    const float* yr = y + (size_t)row * DINNER;
    const float* zr = zx + (size_t)row * DINPROJ;
    const int tid = threadIdx.x;

    float vals[8];
    float ss = 0.f;
#pragma unroll
    for (int i = 0; i < 8; i++) {
        const float v = yr[tid + 256 * i];
        vals[i] = v;
        ss = fmaf(v, v, ss);
    }

    __shared__ float red[256];
    red[tid] = ss;
    __syncthreads();
#pragma unroll
    for (int s = 128; s > 0; s >>= 1) {
        if (tid < s) red[tid] += red[tid + s];
        __syncthreads();
    }
    const float scale = rsqrtf(red[0] / (float)DINNER + RMS_EPS);

#pragma unroll
    for (int i = 0; i < 8; i++) {
        const int c = tid + 256 * i;
        const float zv = zr[c];
        const float gate = 1.f / (1.f + expf(-zv));
        const float out = vals[i] * scale * w[c] * gate;
        const __half h = __float2half_rn(out);
        yhi[(size_t)row * DINNER + c] = h;
        ylo[(size_t)row * DINNER + c] = __float2half_rn(out - __half2float(h));
    }
}

// ================= launch =================
extern "C" void kernel_launch(void* const* d_in, const int* in_sizes, int n_in,
                              void* d_out, int out_size)
{
    const float* u         = (const float*)d_in[0];
    const float* in_proj_w = (const float*)d_in[1];
    const float* conv_w    = (const float*)d_in[2];
    const float* conv_b    = (const float*)d_in[3];
    const float* dt_bias   = (const float*)d_in[4];
    const float* A_log     = (const float*)d_in[5];
    const float* Dv        = (const float*)d_in[6];
    const float* rms_w     = (const float*)d_in[7];
    const float* out_w     = (const float*)d_in[8];
    float* out = (float*)d_out;

    float *zx, *xbc, *dt, *y, *Sb, *hinit, *cum;
    cudaGetSymbolAddress((void**)&zx,    g_zxbcdt);
    cudaGetSymbolAddress((void**)&xbc,   g_xbc);
    cudaGetSymbolAddress((void**)&dt,    g_dt);
    cudaGetSymbolAddress((void**)&y,     g_y);
    cudaGetSymbolAddress((void**)&Sb,    g_S);
    cudaGetSymbolAddress((void**)&hinit, g_hinit);
    cudaGetSymbolAddress((void**)&cum,   g_cum);

    __half *uhi, *ulo, *w1hi, *yhi, *ylo, *w2hi;
    cudaGetSymbolAddress((void**)&uhi,  g_uhi);
    cudaGetSymbolAddress((void**)&ulo,  g_ulo);
    cudaGetSymbolAddress((void**)&w1hi, g_w1hi);
    cudaGetSymbolAddress((void**)&yhi,  g_yhi);
    cudaGetSymbolAddress((void**)&ylo,  g_ylo);
    cudaGetSymbolAddress((void**)&w2hi, g_w2hi);

    cudaFuncSetAttribute(gemm_fused, cudaFuncAttributeMaxDynamicSharedMemorySize, GEMM_SMEM);

    // 1) conversions for GEMM1: u -> fp16 hi/lo; w1 -> fp16 hi (padded)
    {
        long long n = (long long)ROWS * DMODEL;
        split_hilo<<<(unsigned)((n/2 + 255) / 256), 256>>>(u, uhi, ulo, n);
        long long ns = (long long)DINPROJ * DMODEL;
        long long np = (long long)NPAD1 * DMODEL;
        to_half<<<(unsigned)((np/2 + 255) / 256), 256>>>(in_proj_w, w1hi, ns, np);
    }
    // 2) in_proj GEMM: zx[8192,4240] = u * W1^T
    {
        dim3 grid(NPAD1 / 128, ROWS / 128);
        gemm_fused<<<grid, 256, GEMM_SMEM>>>(uhi, ulo, w1hi, zx, DMODEL, DINPROJ, DINPROJ);
    }
    // 3) conv + silu
    {
        const long long total = (long long)ROWS * CONVDIM;
        conv_silu_kernel<<<(unsigned)((total + 255) / 256), 256>>>(zx, conv_w, conv_b, xbc);
    }
    // 4) dt softplus
    dt_kernel<<<(ROWS * NHEADS + 255) / 256, 256>>>(zx, dt_bias, dt);
    // 5) chunk-parallel scan
    scan_chunk<<<BATCH * NHEADS * NC, 256>>>(xbc, dt, A_log, Dv, y, Sb, cum);
    chunk_prefix<<<BATCH * NHEADS, 256>>>(Sb, cum, hinit);
    y_correct<<<BATCH * NHEADS * NC, 256>>>(xbc, hinit, cum, y);
    // 6) rmsnorm + gate -> fp16 hi/lo directly
    rmsgate_kernel<<<ROWS, 256>>>(y, zx, rms_w, yhi, ylo);
    // 7) w2 -> fp16 hi
    {
        long long nw = (long long)DMODEL * DINNER;
        to_half<<<(unsigned)((nw/2 + 255) / 256), 256>>>(out_w, w2hi, nw, nw);
    }
    // 8) out_proj GEMM: out[8192,1024] = y_gated * W2^T
    {
        dim3 grid(DMODEL / 128, ROWS / 128);
        gemm_fused<<<grid, 256, GEMM_SMEM>>>(yhi, ylo, w2hi, out, DINNER, DMODEL, DMODEL);
    }
}

// round 15
// speedup vs baseline: 2.2244x; 1.2618x over previous
#include <cuda_runtime.h>
#include <cuda_fp16.h>
#include <math.h>
#include <stdint.h>

// ---------------- problem constants ----------------
#define BATCH    2
#define SEQLEN   4096
#define DMODEL   1024
#define DINNER   2048
#define DSTATE   64
#define NHEADS   16
#define HEADDIM  128
#define DCONV    4
#define CONVDIM  (DINNER + 2 * DSTATE)          // 2176
#define DINPROJ  (2*DINNER + 2*DSTATE + NHEADS) // 4240
#define NPAD1    4352                           // 34 * 128
#define ROWS     (BATCH * SEQLEN)               // 8192
#define RMS_EPS  1e-5f
#define LC       256                            // scan chunk length
#define NC       (SEQLEN / LC)                  // 16 chunks

// ---------------- scratch (no allocs allowed) ----------------
__device__ float g_zxbcdt[(size_t)ROWS * DINPROJ];
__device__ float g_xbc[(size_t)ROWS * CONVDIM];
__device__ float g_dt[(size_t)ROWS * NHEADS];
__device__ float g_y[(size_t)ROWS * DINNER];

__device__ float g_S[(size_t)BATCH * NHEADS * NC * HEADDIM * DSTATE];
__device__ float g_hinit[(size_t)BATCH * NHEADS * NC * HEADDIM * DSTATE];
__device__ float g_cum[(size_t)BATCH * NHEADS * SEQLEN];

__device__ __half g_uh[(size_t)ROWS * DMODEL];
__device__ __half g_w1h[(size_t)NPAD1 * DMODEL];
__device__ __half g_yh[(size_t)ROWS * DINNER];
__device__ __half g_w2h[(size_t)DMODEL * DINNER];

// ================= helpers =================
__device__ __forceinline__ uint32_t smem_u32(const void* p) {
    uint32_t a;
    asm("{ .reg .u64 t; cvta.to.shared.u64 t, %1; cvt.u32.u64 %0, t; }" : "=r"(a) : "l"(p));
    return a;
}
__device__ __forceinline__ void cp16(uint32_t dst, const void* src) {
    asm volatile("cp.async.ca.shared.global [%0], [%1], 16;" :: "r"(dst), "l"(src));
}
__device__ __forceinline__ void cp_commit() {
    asm volatile("cp.async.commit_group;" ::: "memory");
}
template <int N>
__device__ __forceinline__ void cp_wait() {
    asm volatile("cp.async.wait_group %0;" :: "n"(N) : "memory");
}
__device__ __forceinline__ void ldmx4(uint32_t addr, uint32_t& r0, uint32_t& r1,
                                      uint32_t& r2, uint32_t& r3) {
    asm volatile("ldmatrix.sync.aligned.m8n8.x4.shared.b16 {%0,%1,%2,%3}, [%4];"
                 : "=r"(r0), "=r"(r1), "=r"(r2), "=r"(r3) : "r"(addr));
}
__device__ __forceinline__ void mma_f16(float& d0, float& d1, float& d2, float& d3,
                                        uint32_t a0, uint32_t a1, uint32_t a2, uint32_t a3,
                                        uint32_t b0, uint32_t b1) {
    asm volatile(
        "mma.sync.aligned.m16n8k16.row.col.f32.f16.f16.f32 "
        "{%0,%1,%2,%3}, {%4,%5,%6,%7}, {%8,%9}, {%0,%1,%2,%3};"
        : "+f"(d0), "+f"(d1), "+f"(d2), "+f"(d3)
        : "r"(a0), "r"(a1), "r"(a2), "r"(a3), "r"(b0), "r"(b1));
}

// fp32 -> fp16, with zero padding to n_pad
__global__ void to_half(const float* __restrict__ src, __half* __restrict__ dst,
                        long long n_src, long long n_pad)
{
    long long i = ((long long)blockIdx.x * blockDim.x + threadIdx.x) * 2;
    if (i >= n_pad) return;
    float x0 = (i     < n_src) ? src[i]     : 0.f;
    float x1 = (i + 1 < n_src) ? src[i + 1] : 0.f;
    *(__half2*)(dst + i) = __halves2half2(__float2half_rn(x0), __float2half_rn(x1));
}

// ================= mma.sync fp16 GEMM: C = A*B^T (fp32 accum) =================
// 128x128 tile, BK=32 per chunk, 2 tiles/chunk (A, B). 3-stage cp.async pipeline.
// 8 warps (4M x 2N; 32x64 per warp), 80B row stride (conflict-free ldmatrix).
#define TILEB  (128 * 80)          // 10240 bytes per tile
#define STAGEB (2 * TILEB)         // A, B
#define NSTAGE 3
#define GEMM_SMEM (NSTAGE * STAGEB)   // 61440

__global__ __launch_bounds__(256, 1)
void gemm_f16(const __half* __restrict__ A, const __half* __restrict__ B,
              float* __restrict__ C, int K, int N, int ldc)
{
    extern __shared__ __align__(16) char dynsm[];
    const uint32_t smbase = smem_u32(dynsm);

    const int tid  = threadIdx.x;
    const int wid  = tid >> 5;
    const int lane = tid & 31;
    const int m0 = blockIdx.y * 128;
    const int n0 = blockIdx.x * 128;

    const int mbase = (wid & 3) * 32;
    const int nbase = (wid >> 2) * 64;

    const int lrow  = tid >> 1;
    const int lhalf = tid & 1;

    const int kc = K >> 5;

    float acc[2][8][4];
#pragma unroll
    for (int mt = 0; mt < 2; mt++)
#pragma unroll
        for (int j = 0; j < 8; j++)
#pragma unroll
            for (int q = 0; q < 4; q++) acc[mt][j][q] = 0.f;

    const __half* srcs[2];
    srcs[0] = A + (size_t)(m0 + lrow) * K + lhalf * 16;
    srcs[1] = B + (size_t)(n0 + lrow) * K + lhalf * 16;
    const uint32_t dsto = lrow * 80 + lhalf * 32;

    auto prefetch = [&](int c, int st) {
        const int k0 = c << 5;
        uint32_t sb = smbase + st * STAGEB + dsto;
#pragma unroll
        for (int t = 0; t < 2; t++) {
            const __half* g = srcs[t] + k0;
            cp16(sb,      g);
            cp16(sb + 16, g + 8);
            sb += TILEB;
        }
    };

    prefetch(0, 0); cp_commit();
    if (kc > 1) { prefetch(1, 1); cp_commit(); }

    const uint32_t rsel  = (lane & 15);
    const uint32_t cselo = (lane >> 4) * 16;

    for (int c = 0; c < kc; ++c) {
        const int st = c % NSTAGE;
        if (c + 2 < kc) {
            prefetch(c + 2, (c + 2) % NSTAGE);
            cp_commit();
            cp_wait<2>();
        } else {
            cp_wait<0>();
        }
        __syncthreads();

        const uint32_t aB = smbase + st * STAGEB;
        const uint32_t bB = aB + TILEB;

#pragma unroll
        for (int s = 0; s < 2; ++s) {        // two k16 steps in BK=32
            const uint32_t so = s * 32 + cselo;
            uint32_t a[2][4];
#pragma unroll
            for (int mt = 0; mt < 2; mt++) {
                const uint32_t ro = (mbase + mt * 16 + rsel) * 80 + so;
                ldmx4(aB + ro, a[mt][0], a[mt][1], a[mt][2], a[mt][3]);
            }
            uint32_t b[8][2];
#pragma unroll
            for (int nt = 0; nt < 4; nt++) {
                const uint32_t ro = (nbase + nt * 16 + rsel) * 80 + so;
                uint32_t r0, r1, r2, r3;
                ldmx4(bB + ro, r0, r1, r2, r3);
                b[nt * 2][0] = r0; b[nt * 2][1] = r2;
                b[nt * 2 + 1][0] = r1; b[nt * 2 + 1][1] = r3;
            }
#pragma unroll
            for (int mt = 0; mt < 2; mt++)
#pragma unroll
                for (int j = 0; j < 8; j++)
                    mma_f16(acc[mt][j][0], acc[mt][j][1], acc[mt][j][2], acc[mt][j][3],
                            a[mt][0], a[mt][1], a[mt][2], a[mt][3],
                            b[j][0], b[j][1]);
        }
        __syncthreads();
    }

    // epilogue
#pragma unroll
    for (int mt = 0; mt < 2; mt++) {
        const int rlo = m0 + mbase + mt * 16 + (lane >> 2);
#pragma unroll
        for (int j = 0; j < 8; j++) {
            const int col = n0 + nbase + j * 8 + 2 * (lane & 3);
            if (col < N) {
                *(float2*)(C + (size_t)rlo * ldc + col) =
                    make_float2(acc[mt][j][0], acc[mt][j][1]);
                *(float2*)(C + (size_t)(rlo + 8) * ldc + col) =
                    make_float2(acc[mt][j][2], acc[mt][j][3]);
            }
        }
    }
}

// ================= causal depthwise conv(4) + SiLU =================
__global__ void conv_silu_kernel(const float* __restrict__ zx,
                                 const float* __restrict__ cw,
                                 const float* __restrict__ cb,
                                 float* __restrict__ out)
{
    const long long idx = (long long)blockIdx.x * blockDim.x + threadIdx.x;
    const long long total = (long long)ROWS * CONVDIM;
    if (idx >= total) return;
    const int c  = (int)(idx % CONVDIM);
    const int bl = (int)(idx / CONVDIM);
    const int l  = bl % SEQLEN;
    const int b  = bl / SEQLEN;

    const float* src = zx + ((size_t)b * SEQLEN) * DINPROJ + DINNER + c;
    float acc = cb[c];
#pragma unroll
    for (int k = 0; k < DCONV; k++) {
        const int li = l - (DCONV - 1) + k;
        if (li >= 0) acc = fmaf(cw[c * DCONV + k], src[(size_t)li * DINPROJ], acc);
    }
    out[idx] = acc / (1.f + expf(-acc));
}

// ================= dt = softplus(raw + bias) =================
__global__ void dt_kernel(const float* __restrict__ zx,
                          const float* __restrict__ dt_bias,
                          float* __restrict__ dt)
{
    const int idx = blockIdx.x * blockDim.x + threadIdx.x;
    if (idx >= ROWS * NHEADS) return;
    const int h  = idx % NHEADS;
    const int bl = idx / NHEADS;
    float v = zx[(size_t)bl * DINPROJ + (DINPROJ - NHEADS) + h] + dt_bias[h];
    dt[idx] = (v > 20.f) ? v : log1pf(expf(v));
}

// ================= Phase 1: chunk-local scan =================
__global__ __launch_bounds__(256, 1)
void scan_chunk(const float* __restrict__ xbc, const float* __restrict__ dtb_,
                const float* __restrict__ A_log, const float* __restrict__ Dv,
                float* __restrict__ y, float* __restrict__ Sout,
                float* __restrict__ cumout)
{
    const int c   = blockIdx.x & (NC - 1);
    const int bh  = blockIdx.x >> 4;
    const int h   = bh & 15;
    const int b   = bh >> 4;
    const int tid = threadIdx.x;
    const int p   = tid & 127;
    const int half = tid >> 7;
    const int nb  = half * 32;
    const int t0  = c * LC;

    const float Ah = -expf(A_log[h]);
    const float Dh = Dv[h];

    __shared__ float Bsh[2][64];
    __shared__ float Csh[2][64];
    __shared__ float dts[2];
    __shared__ float yred[128];

    const float* xb  = xbc + (size_t)b * SEQLEN * CONVDIM;
    const float* dtp = dtb_ + (size_t)b * SEQLEN * NHEADS + h;

    float s[32];
#pragma unroll
    for (int i = 0; i < 32; i++) s[i] = 0.f;

    {
        const size_t base = (size_t)t0 * CONVDIM;
        if (tid < 64)        Bsh[0][tid]      = xb[base + DINNER + tid];
        else if (tid < 128)  Csh[0][tid - 64] = xb[base + DINNER + DSTATE + (tid - 64)];
        else if (tid == 128) dts[0]           = dtp[(size_t)t0 * NHEADS];
    }
    __syncthreads();

    float cum = 1.f;
    for (int tt = 0; tt < LC; tt++) {
        const int t   = t0 + tt;
        const int buf = tt & 1;
        const float x = xb[(size_t)t * CONVDIM + h * HEADDIM + p];
        const float decay = expf(dts[buf] * Ah);
        cum *= decay;

        if (tt + 1 < LC) {
            const int nbuf = buf ^ 1;
            const size_t base = (size_t)(t + 1) * CONVDIM;
            if (tid < 64)        Bsh[nbuf][tid]      = xb[base + DINNER + tid];
            else if (tid < 128)  Csh[nbuf][tid - 64] = xb[base + DINNER + DSTATE + (tid - 64)];
            else if (tid == 128) dts[nbuf]           = dtp[(size_t)(t + 1) * NHEADS];
        }

        float yp = 0.f;
        const float4* B4 = (const float4*)&Bsh[buf][nb];
        const float4* C4 = (const float4*)&Csh[buf][nb];
#pragma unroll
        for (int i = 0; i < 8; i++) {
            const float4 bv = B4[i];
            const float4 cv = C4[i];
            s[4*i+0] = fmaf(bv.x, x, decay * s[4*i+0]); yp = fmaf(s[4*i+0], cv.x, yp);
            s[4*i+1] = fmaf(bv.y, x, decay * s[4*i+1]); yp = fmaf(s[4*i+1], cv.y, yp);
            s[4*i+2] = fmaf(bv.z, x, decay * s[4*i+2]); yp = fmaf(s[4*i+2], cv.z, yp);
            s[4*i+3] = fmaf(bv.w, x, decay * s[4*i+3]); yp = fmaf(s[4*i+3], cv.w, yp);
        }

        if (tid == 255) cumout[(size_t)bh * SEQLEN + t] = cum;

        if (half) yred[p] = yp;
        __syncthreads();
        if (!half) {
            const float out = yp + yred[p] + Dh * x;
            y[((size_t)b * SEQLEN + t) * DINNER + h * HEADDIM + p] = out;
        }
        __syncthreads();
    }

    {
        float* Sp = Sout + (((size_t)(bh * NC + c)) << 13) + p * 64 + nb;
#pragma unroll
        for (int i = 0; i < 32; i += 4)
            *(float4*)(Sp + i) = make_float4(s[i], s[i+1], s[i+2], s[i+3]);
    }
}

// ================= Phase 2: inter-chunk state prefix =================
__global__ __launch_bounds__(256)
void chunk_prefix(const float* __restrict__ S, const float* __restrict__ cumb,
                  float* __restrict__ hinit)
{
    const int bh  = blockIdx.x;
    const int tid = threadIdx.x;

    float hreg[32];
#pragma unroll
    for (int j = 0; j < 32; j++) hreg[j] = 0.f;

    for (int c = 0; c < NC; c++) {
        const float Ac = cumb[(size_t)bh * SEQLEN + c * LC + LC - 1];
        const size_t base = ((size_t)(bh * NC + c)) << 13;
#pragma unroll
        for (int j = 0; j < 32; j++) {
            const size_t idx = base + tid + 256 * j;
            hinit[idx] = hreg[j];
            hreg[j] = fmaf(Ac, hreg[j], S[idx]);
        }
    }
}

// ================= Phase 3: y += cum_t * (C_t . h_init) =================
__global__ __launch_bounds__(256)
void y_correct(const float* __restrict__ xbc, const float* __restrict__ hinit,
               const float* __restrict__ cumb, float* __restrict__ y)
{
    const int c = blockIdx.x & (NC - 1);
    if (c == 0) return;
    const int bh  = blockIdx.x >> 4;
    const int h   = bh & 15;
    const int b   = bh >> 4;
    const int tid = threadIdx.x;
    const int p   = tid >> 1;
    const int nh  = (tid & 1) * 32;
    const int t0  = c * LC;

    __shared__ float Cs[2][64];

    float hreg[32];
    {
        const float* hp = hinit + (((size_t)(bh * NC + c)) << 13) + p * 64 + nh;
#pragma unroll
        for (int i = 0; i < 32; i += 4) {
            float4 v = *(const float4*)(hp + i);
            hreg[i] = v.x; hreg[i+1] = v.y; hreg[i+2] = v.z; hreg[i+3] = v.w;
        }
    }

    const float* xb = xbc + (size_t)b * SEQLEN * CONVDIM;
    if (tid < 64) Cs[0][tid] = xb[(size_t)t0 * CONVDIM + DINNER + DSTATE + tid];
    __syncthreads();

    const float* cumrow = cumb + (size_t)bh * SEQLEN;

    for (int tt = 0; tt < LC; tt++) {
        const int t   = t0 + tt;
        const int buf = tt & 1;
        if (tt + 1 < LC && tid < 64)
            Cs[buf ^ 1][tid] = xb[(size_t)(t + 1) * CONVDIM + DINNER + DSTATE + tid];

        float dot = 0.f;
        const float4* C4 = (const float4*)&Cs[buf][nh];
#pragma unroll
        for (int k = 0; k < 8; k++) {
            const float4 cv = C4[k];
            dot = fmaf(hreg[4*k+0], cv.x, dot);
            dot = fmaf(hreg[4*k+1], cv.y, dot);
            dot = fmaf(hreg[4*k+2], cv.z, dot);
            dot = fmaf(hreg[4*k+3], cv.w, dot);
        }
        dot += __shfl_xor_sync(0xffffffffu, dot, 1);

        if ((tid & 1) == 0) {
            float* yp = y + ((size_t)b * SEQLEN + t) * DINNER + h * HEADDIM + p;
            *yp += cumrow[t] * dot;
        }
        __syncthreads();
    }
}

// ================= RMSNorm + SiLU(z) gate -> fp16 =================
__global__ __launch_bounds__(256)
void rmsgate_kernel(const float* __restrict__ y, const float* __restrict__ zx,
                    const float* __restrict__ w, __half* __restrict__ yh)
{
    const int row = blockIdx.x;
    const float* yr = y + (size_t)row * DINNER;
    const float* zr = zx + (size_t)row * DINPROJ;
    const int tid = threadIdx.x;

    float vals[8];
    float ss = 0.f;
#pragma unroll
    for (int i = 0; i < 8; i++) {
        const float v = yr[tid + 256 * i];
        vals[i] = v;
        ss = fmaf(v, v, ss);
    }

    __shared__ float red[256];
    red[tid] = ss;
    __syncthreads();
#pragma unroll
    for (int s = 128; s > 0; s >>= 1) {
        if (tid < s) red[tid] += red[tid + s];
        __syncthreads();
    }
    const float scale = rsqrtf(red[0] / (float)DINNER + RMS_EPS);

#pragma unroll
    for (int i = 0; i < 8; i++) {
        const int c = tid + 256 * i;
        const float zv = zr[c];
        const float gate = 1.f / (1.f + expf(-zv));
        const float out = vals[i] * scale * w[c] * gate;
        yh[(size_t)row * DINNER + c] = __float2half_rn(out);
    }
}

// ================= launch =================
extern "C" void kernel_launch(void* const* d_in, const int* in_sizes, int n_in,
                              void* d_out, int out_size)
{
    const float* u         = (const float*)d_in[0];
    const float* in_proj_w = (const float*)d_in[1];
    const float* conv_w    = (const float*)d_in[2];
    const float* conv_b    = (const float*)d_in[3];
    const float* dt_bias   = (const float*)d_in[4];
    const float* A_log     = (const float*)d_in[5];
    const float* Dv        = (const float*)d_in[6];
    const float* rms_w     = (const float*)d_in[7];
    const float* out_w     = (const float*)d_in[8];
    float* out = (float*)d_out;

    float *zx, *xbc, *dt, *y, *Sb, *hinit, *cum;
    cudaGetSymbolAddress((void**)&zx,    g_zxbcdt);
    cudaGetSymbolAddress((void**)&xbc,   g_xbc);
    cudaGetSymbolAddress((void**)&dt,    g_dt);
    cudaGetSymbolAddress((void**)&y,     g_y);
    cudaGetSymbolAddress((void**)&Sb,    g_S);
    cudaGetSymbolAddress((void**)&hinit, g_hinit);
    cudaGetSymbolAddress((void**)&cum,   g_cum);

    __half *uh, *w1h, *yh, *w2h;
    cudaGetSymbolAddress((void**)&uh,  g_uh);
    cudaGetSymbolAddress((void**)&w1h, g_w1h);
    cudaGetSymbolAddress((void**)&yh,  g_yh);
    cudaGetSymbolAddress((void**)&w2h, g_w2h);

    cudaFuncSetAttribute(gemm_f16, cudaFuncAttributeMaxDynamicSharedMemorySize, GEMM_SMEM);

    // 1) conversions for GEMM1
    {
        long long n = (long long)ROWS * DMODEL;
        to_half<<<(unsigned)((n/2 + 255) / 256), 256>>>(u, uh, n, n);
        long long ns = (long long)DINPROJ * DMODEL;
        long long np = (long long)NPAD1 * DMODEL;
        to_half<<<(unsigned)((np/2 + 255) / 256), 256>>>(in_proj_w, w1h, ns, np);
    }
    // 2) in_proj GEMM: zx[8192,4240] = u * W1^T
    {
        dim3 grid(NPAD1 / 128, ROWS / 128);
        gemm_f16<<<grid, 256, GEMM_SMEM>>>(uh, w1h, zx, DMODEL, DINPROJ, DINPROJ);
    }
    // 3) conv + silu
    {
        const long long total = (long long)ROWS * CONVDIM;
        conv_silu_kernel<<<(unsigned)((total + 255) / 256), 256>>>(zx, conv_w, conv_b, xbc);
    }
    // 4) dt softplus
    dt_kernel<<<(ROWS * NHEADS + 255) / 256, 256>>>(zx, dt_bias, dt);
    // 5) chunk-parallel scan
    scan_chunk<<<BATCH * NHEADS * NC, 256>>>(xbc, dt, A_log, Dv, y, Sb, cum);
    chunk_prefix<<<BATCH * NHEADS, 256>>>(Sb, cum, hinit);
    y_correct<<<BATCH * NHEADS * NC, 256>>>(xbc, hinit, cum, y);
    // 6) rmsnorm + gate -> fp16
    rmsgate_kernel<<<ROWS, 256>>>(y, zx, rms_w, yh);
    // 7) w2 -> fp16
    {
        long long nw = (long long)DMODEL * DINNER;
        to_half<<<(unsigned)((nw/2 + 255) / 256), 256>>>(out_w, w2h, nw, nw);
    }
    // 8) out_proj GEMM: out[8192,1024] = y_gated * W2^T
    {
        dim3 grid(DMODEL / 128, ROWS / 128);
        gemm_f16<<<grid, 256, GEMM_SMEM>>>(yh, w2h, out, DINNER, DMODEL, DMODEL);
    }
}